// round 14
// baseline (speedup 1.0000x reference)
#include <cuda_runtime.h>

// FlowNetC correlation: out[b, dy*21+dx, y, x] =
//   (1/256) * sum_c in1[b,c,y,x] * in2[b,c, y+2dy-20, x+2dx-20]   (zero-padded)
// B=16 C=256 H=48 W=64, 21x21 displacements.

#define BB 16
#define CC 256
#define HH 48
#define WW 64
#define ND 21

#define CHUNK 8            // channels per smem stage
#define ROWF  108          // padded floats per in2 row in smem (104 used)
#define S1CH  64           // floats per channel for the in1 row
#define S1BUF (CHUNK*S1CH)       // 512
#define S2ROW (ND*ROWF)          // 2268
#define S2BUF (CHUNK*S2ROW)      // 18144
#define SMEM_FLOATS (2*(S1BUF+S2BUF))   // 37312
#define SMEM_BYTES  (SMEM_FLOATS*4)     // 149248

typedef unsigned long long ull;

// Packed 2xfp32 FMA (Blackwell f32x2 pipe) — doubles fp32 throughput vs FFMA.
__device__ __forceinline__ ull ffma2(ull a, ull b, ull c) {
    ull d;
    asm("fma.rn.f32x2 %0, %1, %2, %3;" : "=l"(d) : "l"(a), "l"(b), "l"(c));
    return d;
}

// 16B cp.async with zero-fill when invalid (src-size = 0 -> no read, zeros).
__device__ __forceinline__ void cp16(float* dst, const float* src, bool v) {
    unsigned sa = (unsigned)__cvta_generic_to_shared(dst);
    int sz = v ? 16 : 0;
    asm volatile("cp.async.cg.shared.global [%0], [%1], 16, %2;"
                 :: "r"(sa), "l"(src), "r"(sz));
}

__global__ __launch_bounds__(512, 1)
void corr_kernel(const float* __restrict__ in1,
                 const float* __restrict__ in2,
                 float* __restrict__ out)
{
    extern __shared__ float smem[];
    float* s1 = smem;               // [2][CHUNK][64]
    float* s2 = smem + 2 * S1BUF;   // [2][CHUNK][ND][ROWF]

    const int y = blockIdx.x;       // 0..47
    const int b = blockIdx.y;       // 0..15
    const int t = threadIdx.x;      // 0..511

    // Compute-role decode: 8 x-groups x 21 dy x 3 dx-groups(7 dx each) = 504 slots.
    const int xg  = t / 63;          // 0..7  (when active)
    const int r   = t - xg * 63;     // 0..62
    const int dyi = r / 3;           // 0..20
    const int dxg = r - dyi * 3;     // 0..2
    const int u0  = xg * 8 + 14 * dxg;   // start index into padded in2 row
    const bool active = (t < 504);

    const int base1 = ((b * CC) * HH + y) * WW;   // in1 base for c=0

    ull acc[28];   // [j=0..6 dx][i=0..3 pixel-pairs] packed f32x2 accumulators
#pragma unroll
    for (int i = 0; i < 28; ++i) acc[i] = 0ull;

    // ---- async loader for one C-chunk into buffer buf ----
    auto load_chunk = [&](int ch, int buf) {
        const int c0 = ch * CHUNK;
        float* s1b = s1 + buf * S1BUF;
        float* s2b = s2 + buf * S2BUF;
        // in1 row: CHUNK x 64 floats = 128 float4
        if (t < 128) {
            int c  = t >> 4;
            int xq = t & 15;
            cp16(s1b + c * S1CH + xq * 4,
                 in1 + base1 + (c0 + c) * (HH * WW) + xq * 4, true);
        }
        // in2: CHUNK x 21 rows x 26 float4 (104 floats valid window, zero halo)
        for (int idx = t; idx < CHUNK * ND * 26; idx += 512) {
            int c   = idx / (ND * 26);
            int rem = idx - c * (ND * 26);
            int dy  = rem / 26;
            int g   = rem - dy * 26;
            int u   = g * 4;                 // padded x index (x2 = u - 20)
            int y2  = y + 2 * dy - 20;
            bool valid = (g >= 5) && (g < 21) && (y2 >= 0) && (y2 < HH);
            const float* src = valid
                ? (in2 + ((b * CC + c0 + c) * HH + y2) * WW + (u - 20))
                : in2;   // not dereferenced when src-size==0
            cp16(s2b + c * S2ROW + dy * ROWF + u, src, valid);
        }
        asm volatile("cp.async.commit_group;");
    };

    load_chunk(0, 0);

    for (int ch = 0; ch < CC / CHUNK; ++ch) {
        const int buf = ch & 1;
        if (ch < CC / CHUNK - 1) {
            load_chunk(ch + 1, buf ^ 1);
            asm volatile("cp.async.wait_group 1;");   // current chunk landed
        } else {
            asm volatile("cp.async.wait_group 0;");
        }
        __syncthreads();

        if (active) {
            const float* s1p = s1 + buf * S1BUF + xg * 8;
            const float* s2p = s2 + buf * S2BUF + dyi * ROWF + u0;
#pragma unroll
            for (int c = 0; c < CHUNK; ++c) {
                ull q[4], kw[10];
#pragma unroll
                for (int i = 0; i < 4; ++i)
                    q[i] = *(const ull*)(s1p + c * S1CH + 2 * i);
#pragma unroll
                for (int m = 0; m < 10; ++m)
                    kw[m] = *(const ull*)(s2p + c * S2ROW + 2 * m);
                // acc[j][i] += (in1 pixel pair i) * (in2 window pair i+j)
#pragma unroll
                for (int j = 0; j < 7; ++j)
#pragma unroll
                    for (int i = 0; i < 4; ++i)
                        acc[j * 4 + i] = ffma2(q[i], kw[i + j], acc[j * 4 + i]);
            }
        }
        __syncthreads();   // protect buffer reuse two iterations later
    }

    if (active) {
        const int d0 = dyi * ND + dxg * 7;
        const float sc = 1.0f / 256.0f;
#pragma unroll
        for (int j = 0; j < 7; ++j) {
            float* op = out + ((b * 441 + d0 + j) * HH + y) * WW + xg * 8;
#pragma unroll
            for (int i = 0; i < 4; ++i) {
                float2 v = *(float2*)&acc[j * 4 + i];
                v.x *= sc; v.y *= sc;
                *(float2*)(op + 2 * i) = v;
            }
        }
    }
}

extern "C" void kernel_launch(void* const* d_in, const int* in_sizes, int n_in,
                              void* d_out, int out_size)
{
    const float* in1 = (const float*)d_in[0];
    const float* in2 = (const float*)d_in[1];
    float* out = (float*)d_out;

    cudaFuncSetAttribute(corr_kernel,
                         cudaFuncAttributeMaxDynamicSharedMemorySize,
                         SMEM_BYTES);

    dim3 grid(HH, BB);   // 48 x 16 = 768 blocks, one (b, y) row each
    corr_kernel<<<grid, 512, SMEM_BYTES>>>(in1, in2, out);
}

// round 15
// speedup vs baseline: 1.0026x; 1.0026x over previous
#include <cuda_runtime.h>

// FlowNetC correlation: out[b, dy*21+dx, y, x] =
//   (1/256) * sum_c in1[b,c,y,x] * in2[b,c, y+2dy-20, x+2dx-20]   (zero-padded)
// B=16 C=256 H=48 W=64, 21x21 displacements.

#define BB 16
#define CC 256
#define HH 48
#define WW 64
#define ND 21

#define CHUNK 8            // channels per smem stage
#define ROWF  108          // padded floats per in2 row in smem (104 used)
#define S1CH  64           // floats per channel for the in1 row
#define S1BUF (CHUNK*S1CH)       // 512
#define S2ROW (ND*ROWF)          // 2268
#define S2BUF (CHUNK*S2ROW)      // 18144
#define SMEM_FLOATS (2*(S1BUF+S2BUF))   // 37312
#define SMEM_BYTES  (SMEM_FLOATS*4)     // 149248

typedef unsigned long long ull;

// Packed 2xfp32 FMA (Blackwell f32x2 pipe) — doubles fp32 throughput vs FFMA.
__device__ __forceinline__ ull ffma2(ull a, ull b, ull c) {
    ull d;
    asm("fma.rn.f32x2 %0, %1, %2, %3;" : "=l"(d) : "l"(a), "l"(b), "l"(c));
    return d;
}

// 16B cp.async with zero-fill when invalid (src-size = 0 -> no read, zeros).
__device__ __forceinline__ void cp16(float* dst, const float* src, bool v) {
    unsigned sa = (unsigned)__cvta_generic_to_shared(dst);
    int sz = v ? 16 : 0;
    asm volatile("cp.async.cg.shared.global [%0], [%1], 16, %2;"
                 :: "r"(sa), "l"(src), "r"(sz));
}

__global__ __launch_bounds__(512, 1)
void corr_kernel(const float* __restrict__ in1,
                 const float* __restrict__ in2,
                 float* __restrict__ out)
{
    extern __shared__ float smem[];
    float* s1 = smem;               // [2][CHUNK][64]
    float* s2 = smem + 2 * S1BUF;   // [2][CHUNK][ND][ROWF]

    const int y = blockIdx.x;       // 0..47
    const int b = blockIdx.y;       // 0..15
    const int t = threadIdx.x;      // 0..511

    // Compute-role decode: 8 x-groups x 21 dy x 3 dx-groups(7 dx each) = 504 slots.
    const int xg  = t / 63;          // 0..7  (when active)
    const int r   = t - xg * 63;     // 0..62
    const int dyi = r / 3;           // 0..20
    const int dxg = r - dyi * 3;     // 0..2
    const int u0  = xg * 8 + 14 * dxg;   // start index into padded in2 row
    const bool active = (t < 504);

    const int base1 = ((b * CC) * HH + y) * WW;   // in1 base for c=0

    ull acc[28];   // [j=0..6 dx][i=0..3 pixel-pairs] packed f32x2 accumulators
#pragma unroll
    for (int i = 0; i < 28; ++i) acc[i] = 0ull;

    // ---- async loader for one C-chunk into buffer buf ----
    auto load_chunk = [&](int ch, int buf) {
        const int c0 = ch * CHUNK;
        float* s1b = s1 + buf * S1BUF;
        float* s2b = s2 + buf * S2BUF;
        // in1 row: CHUNK x 64 floats = 128 float4
        if (t < 128) {
            int c  = t >> 4;
            int xq = t & 15;
            cp16(s1b + c * S1CH + xq * 4,
                 in1 + base1 + (c0 + c) * (HH * WW) + xq * 4, true);
        }
        // in2: CHUNK x 21 rows x 26 float4 (104 floats valid window, zero halo)
        for (int idx = t; idx < CHUNK * ND * 26; idx += 512) {
            int c   = idx / (ND * 26);
            int rem = idx - c * (ND * 26);
            int dy  = rem / 26;
            int g   = rem - dy * 26;
            int u   = g * 4;                 // padded x index (x2 = u - 20)
            int y2  = y + 2 * dy - 20;
            bool valid = (g >= 5) && (g < 21) && (y2 >= 0) && (y2 < HH);
            const float* src = valid
                ? (in2 + ((b * CC + c0 + c) * HH + y2) * WW + (u - 20))
                : in2;   // not dereferenced when src-size==0
            cp16(s2b + c * S2ROW + dy * ROWF + u, src, valid);
        }
        asm volatile("cp.async.commit_group;");
    };

    load_chunk(0, 0);

    for (int ch = 0; ch < CC / CHUNK; ++ch) {
        const int buf = ch & 1;
        if (ch < CC / CHUNK - 1) {
            load_chunk(ch + 1, buf ^ 1);
            asm volatile("cp.async.wait_group 1;");   // current chunk landed
        } else {
            asm volatile("cp.async.wait_group 0;");
        }
        __syncthreads();

        if (active) {
            const float* s1p = s1 + buf * S1BUF + xg * 8;
            const float* s2p = s2 + buf * S2BUF + dyi * ROWF + u0;
#pragma unroll
            for (int c = 0; c < CHUNK; ++c) {
                ull q[4], kw[10];
#pragma unroll
                for (int i = 0; i < 4; ++i)
                    q[i] = *(const ull*)(s1p + c * S1CH + 2 * i);
#pragma unroll
                for (int m = 0; m < 10; ++m)
                    kw[m] = *(const ull*)(s2p + c * S2ROW + 2 * m);
                // acc[j][i] += (in1 pixel pair i) * (in2 window pair i+j)
#pragma unroll
                for (int j = 0; j < 7; ++j)
#pragma unroll
                    for (int i = 0; i < 4; ++i)
                        acc[j * 4 + i] = ffma2(q[i], kw[i + j], acc[j * 4 + i]);
            }
        }
        __syncthreads();   // protect buffer reuse two iterations later
    }

    if (active) {
        const int d0 = dyi * ND + dxg * 7;
        const float sc = 1.0f / 256.0f;
#pragma unroll
        for (int j = 0; j < 7; ++j) {
            float* op = out + ((b * 441 + d0 + j) * HH + y) * WW + xg * 8;
#pragma unroll
            for (int i = 0; i < 4; ++i) {
                float2 v = *(float2*)&acc[j * 4 + i];
                v.x *= sc; v.y *= sc;
                *(float2*)(op + 2 * i) = v;
            }
        }
    }
}

extern "C" void kernel_launch(void* const* d_in, const int* in_sizes, int n_in,
                              void* d_out, int out_size)
{
    const float* in1 = (const float*)d_in[0];
    const float* in2 = (const float*)d_in[1];
    float* out = (float*)d_out;

    cudaFuncSetAttribute(corr_kernel,
                         cudaFuncAttributeMaxDynamicSharedMemorySize,
                         SMEM_BYTES);

    dim3 grid(HH, BB);   // 48 x 16 = 768 blocks, one (b, y) row each
    corr_kernel<<<grid, 512, SMEM_BYTES>>>(in1, in2, out);
}

// round 16
// speedup vs baseline: 1.0032x; 1.0006x over previous
#include <cuda_runtime.h>

// FlowNetC correlation: out[b, dy*21+dx, y, x] =
//   (1/256) * sum_c in1[b,c,y,x] * in2[b,c, y+2dy-20, x+2dx-20]   (zero-padded)
// B=16 C=256 H=48 W=64, 21x21 displacements.

#define BB 16
#define CC 256
#define HH 48
#define WW 64
#define ND 21

#define CHUNK 8            // channels per smem stage
#define ROWF  108          // padded floats per in2 row in smem (104 used)
#define S1CH  64           // floats per channel for the in1 row
#define S1BUF (CHUNK*S1CH)       // 512
#define S2ROW (ND*ROWF)          // 2268
#define S2BUF (CHUNK*S2ROW)      // 18144
#define SMEM_FLOATS (2*(S1BUF+S2BUF))   // 37312
#define SMEM_BYTES  (SMEM_FLOATS*4)     // 149248

typedef unsigned long long ull;

// Packed 2xfp32 FMA (Blackwell f32x2 pipe) — doubles fp32 throughput vs FFMA.
__device__ __forceinline__ ull ffma2(ull a, ull b, ull c) {
    ull d;
    asm("fma.rn.f32x2 %0, %1, %2, %3;" : "=l"(d) : "l"(a), "l"(b), "l"(c));
    return d;
}

// 16B cp.async with zero-fill when invalid (src-size = 0 -> no read, zeros).
__device__ __forceinline__ void cp16(float* dst, const float* src, bool v) {
    unsigned sa = (unsigned)__cvta_generic_to_shared(dst);
    int sz = v ? 16 : 0;
    asm volatile("cp.async.cg.shared.global [%0], [%1], 16, %2;"
                 :: "r"(sa), "l"(src), "r"(sz));
}

__global__ __launch_bounds__(512, 1)
void corr_kernel(const float* __restrict__ in1,
                 const float* __restrict__ in2,
                 float* __restrict__ out)
{
    extern __shared__ float smem[];
    float* s1 = smem;               // [2][CHUNK][64]
    float* s2 = smem + 2 * S1BUF;   // [2][CHUNK][ND][ROWF]

    const int y = blockIdx.x;       // 0..47
    const int b = blockIdx.y;       // 0..15
    const int t = threadIdx.x;      // 0..511

    // Compute-role decode: 8 x-groups x 21 dy x 3 dx-groups(7 dx each) = 504 slots.
    const int xg  = t / 63;          // 0..7  (when active)
    const int r   = t - xg * 63;     // 0..62
    const int dyi = r / 3;           // 0..20
    const int dxg = r - dyi * 3;     // 0..2
    const int u0  = xg * 8 + 14 * dxg;   // start index into padded in2 row
    const bool active = (t < 504);

    const int base1 = ((b * CC) * HH + y) * WW;   // in1 base for c=0

    ull acc[28];   // [j=0..6 dx][i=0..3 pixel-pairs] packed f32x2 accumulators
#pragma unroll
    for (int i = 0; i < 28; ++i) acc[i] = 0ull;

    // ---- async loader for one C-chunk into buffer buf ----
    auto load_chunk = [&](int ch, int buf) {
        const int c0 = ch * CHUNK;
        float* s1b = s1 + buf * S1BUF;
        float* s2b = s2 + buf * S2BUF;
        // in1 row: CHUNK x 64 floats = 128 float4
        if (t < 128) {
            int c  = t >> 4;
            int xq = t & 15;
            cp16(s1b + c * S1CH + xq * 4,
                 in1 + base1 + (c0 + c) * (HH * WW) + xq * 4, true);
        }
        // in2: CHUNK x 21 rows x 26 float4 (104 floats valid window, zero halo)
        for (int idx = t; idx < CHUNK * ND * 26; idx += 512) {
            int c   = idx / (ND * 26);
            int rem = idx - c * (ND * 26);
            int dy  = rem / 26;
            int g   = rem - dy * 26;
            int u   = g * 4;                 // padded x index (x2 = u - 20)
            int y2  = y + 2 * dy - 20;
            bool valid = (g >= 5) && (g < 21) && (y2 >= 0) && (y2 < HH);
            const float* src = valid
                ? (in2 + ((b * CC + c0 + c) * HH + y2) * WW + (u - 20))
                : in2;   // not dereferenced when src-size==0
            cp16(s2b + c * S2ROW + dy * ROWF + u, src, valid);
        }
        asm volatile("cp.async.commit_group;");
    };

    load_chunk(0, 0);

    for (int ch = 0; ch < CC / CHUNK; ++ch) {
        const int buf = ch & 1;
        if (ch < CC / CHUNK - 1) {
            load_chunk(ch + 1, buf ^ 1);
            asm volatile("cp.async.wait_group 1;");   // current chunk landed
        } else {
            asm volatile("cp.async.wait_group 0;");
        }
        __syncthreads();

        if (active) {
            const float* s1p = s1 + buf * S1BUF + xg * 8;
            const float* s2p = s2 + buf * S2BUF + dyi * ROWF + u0;
#pragma unroll
            for (int c = 0; c < CHUNK; ++c) {
                ull q[4], kw[10];
#pragma unroll
                for (int i = 0; i < 4; ++i)
                    q[i] = *(const ull*)(s1p + c * S1CH + 2 * i);
#pragma unroll
                for (int m = 0; m < 10; ++m)
                    kw[m] = *(const ull*)(s2p + c * S2ROW + 2 * m);
                // acc[j][i] += (in1 pixel pair i) * (in2 window pair i+j)
#pragma unroll
                for (int j = 0; j < 7; ++j)
#pragma unroll
                    for (int i = 0; i < 4; ++i)
                        acc[j * 4 + i] = ffma2(q[i], kw[i + j], acc[j * 4 + i]);
            }
        }
        __syncthreads();   // protect buffer reuse two iterations later
    }

    if (active) {
        const int d0 = dyi * ND + dxg * 7;
        const float sc = 1.0f / 256.0f;
#pragma unroll
        for (int j = 0; j < 7; ++j) {
            float* op = out + ((b * 441 + d0 + j) * HH + y) * WW + xg * 8;
#pragma unroll
            for (int i = 0; i < 4; ++i) {
                float2 v = *(float2*)&acc[j * 4 + i];
                v.x *= sc; v.y *= sc;
                *(float2*)(op + 2 * i) = v;
            }
        }
    }
}

extern "C" void kernel_launch(void* const* d_in, const int* in_sizes, int n_in,
                              void* d_out, int out_size)
{
    const float* in1 = (const float*)d_in[0];
    const float* in2 = (const float*)d_in[1];
    float* out = (float*)d_out;

    cudaFuncSetAttribute(corr_kernel,
                         cudaFuncAttributeMaxDynamicSharedMemorySize,
                         SMEM_BYTES);

    dim3 grid(HH, BB);   // 48 x 16 = 768 blocks, one (b, y) row each
    corr_kernel<<<grid, 512, SMEM_BYTES>>>(in1, in2, out);
}